// round 1
// baseline (speedup 1.0000x reference)
#include <cuda_runtime.h>

// Problem shape (fixed by setup_inputs): B=16, N=32, H=W=256
#define HH 256
#define WW 256
#define BB 16
#define NN 32
#define ROWS (BB * NN)      // 512 (b,n) planes
#define PLANE (HH * WW)     // 65536

// ---------------------------------------------------------------------------
// Kernel 1: zero the whole output (134 MB) with vectorized 128-bit stores.
// This is the bandwidth-bound part; everything else is noise.
// ---------------------------------------------------------------------------
__global__ void zero_kernel(float4* __restrict__ out, int n4) {
    int i = blockIdx.x * blockDim.x + threadIdx.x;
    if (i < n4) out[i] = make_float4(0.f, 0.f, 0.f, 0.f);
}

// ---------------------------------------------------------------------------
// Kernel 2: analytic sparse evaluation. One block per (b,n) row.
//   xy       = gather of the matched keypoint (warp reduction over one-hot row)
//   corners  = clipped floor/ceil, bilinear weights (may exceed [0,1] at edges,
//              exactly like the reference after clipping)
//   output   = for each pixel in the <=6x6 affected window:
//              sum over 4 corners of w_corner * GK5[corner - pixel + 2]
// Planes are disjoint per (b,n) -> plain stores, no atomics.
// ---------------------------------------------------------------------------
__global__ void sparse_kernel(const float* __restrict__ Xg,
                              const float* __restrict__ kp,
                              const float* __restrict__ gk,
                              float* __restrict__ out) {
    __shared__ float s_gk[25];
    __shared__ float s_red[3];   // sum(Xg*kx), sum(Xg*ky), sum(Xg) = mask

    const int row = blockIdx.x;      // b*N + n
    const int b   = row >> 5;        // N = 32
    const int tid = threadIdx.x;

    if (tid < 25) s_gk[tid] = gk[tid];   // gk[0][0] plane: the 5x5 kernel

    if (tid < 32) {
        float xg = Xg[row * NN + tid];
        float kx = kp[(b * NN + tid) * 2 + 0];
        float ky = kp[(b * NN + tid) * 2 + 1];
        float sx = xg * kx, sy = xg * ky, sm = xg;
        #pragma unroll
        for (int o = 16; o; o >>= 1) {
            sx += __shfl_down_sync(0xffffffffu, sx, o);
            sy += __shfl_down_sync(0xffffffffu, sy, o);
            sm += __shfl_down_sync(0xffffffffu, sm, o);
        }
        if (tid == 0) { s_red[0] = sx; s_red[1] = sy; s_red[2] = sm; }
    }
    __syncthreads();

    const float mask = s_red[2];
    if (mask == 0.f) return;   // row is fully masked -> stays zero

    const float x = s_red[0] * (1.f / 16.f) - 0.5f;
    const float y = s_red[1] * (1.f / 16.f) - 0.5f;

    const float lox = fminf(fmaxf(floorf(x), 0.f), (float)(WW - 1));
    const float loy = fminf(fmaxf(floorf(y), 0.f), (float)(HH - 1));
    const float hix = fminf(fmaxf(ceilf(x),  0.f), (float)(WW - 1));
    const float hiy = fminf(fmaxf(ceilf(y),  0.f), (float)(HH - 1));

    const float upx = x - lox, upy = y - loy;
    const float wx0 = 1.f - upx, wx1 = upx;
    const float wy0 = 1.f - upy, wy1 = upy;

    const int x0 = (int)lox, x1 = (int)hix;
    const int y0 = (int)loy, y1 = (int)hiy;

    // affected window: rows [y0-2, y1+2], cols [x0-2, x1+2]  (y1-y0, x1-x0 <= 1)
    const int nx = x1 - x0 + 5;
    const int ny = y1 - y0 + 5;
    const int npix = nx * ny;                // <= 36

    float* plane = out + (size_t)row * PLANE;

    for (int p = tid; p < npix; p += blockDim.x) {
        const int dy = p / nx, dx = p - dy * nx;
        const int oy = y0 - 2 + dy;
        const int ox = x0 - 2 + dx;
        if (oy < 0 || oy >= HH || ox < 0 || ox >= WW) continue;

        // kernel taps per corner (kernel is 180deg-symmetric, orientation moot)
        const int ry0 = oy - y0 + 2, ry1 = oy - y1 + 2;
        const int rx0 = ox - x0 + 2, rx1 = ox - x1 + 2;

        const bool by0 = (ry0 >= 0) & (ry0 < 5);
        const bool by1 = (ry1 >= 0) & (ry1 < 5);
        const bool bx0 = (rx0 >= 0) & (rx0 < 5);
        const bool bx1 = (rx1 >= 0) & (rx1 < 5);

        const float g00 = (by0 & bx0) ? s_gk[ry0 * 5 + rx0] : 0.f;
        const float g01 = (by0 & bx1) ? s_gk[ry0 * 5 + rx1] : 0.f;
        const float g10 = (by1 & bx0) ? s_gk[ry1 * 5 + rx0] : 0.f;
        const float g11 = (by1 & bx1) ? s_gk[ry1 * 5 + rx1] : 0.f;

        const float v = wy0 * wx0 * g00 + wy0 * wx1 * g01
                      + wy1 * wx0 * g10 + wy1 * wx1 * g11;

        plane[oy * WW + ox] = v * mask;   // mask == 1 here
    }
}

extern "C" void kernel_launch(void* const* d_in, const int* in_sizes, int n_in,
                              void* d_out, int out_size) {
    const float* Xg = (const float*)d_in[0];   // (B, N, N)
    const float* kp = (const float*)d_in[1];   // (B, N, 2)
    const float* gk = (const float*)d_in[2];   // (N, 1, 5, 5)
    float* out = (float*)d_out;                // (B, N, H*W) fp32

    const int n4 = out_size / 4;               // out_size = 33,554,432 (div by 4)
    const int threads = 256;
    const int blocks = (n4 + threads - 1) / threads;
    zero_kernel<<<blocks, threads>>>((float4*)out, n4);
    sparse_kernel<<<ROWS, 64>>>(Xg, kp, gk, out);
}

// round 2
// speedup vs baseline: 1.3615x; 1.3615x over previous
#include <cuda_runtime.h>

// Problem shape (fixed by setup_inputs): B=16, N=32, H=W=256
#define HH 256
#define WW 256
#define BB 16
#define NN 32
#define ROWS (BB * NN)        // 512 (b,n) planes
#define PLANE (HH * WW)       // 65536 floats = 256 KB per plane
#define THREADS 256
#define F4_PER_PLANE (PLANE / 4)          // 16384
#define ITERS (F4_PER_PLANE / THREADS)    // 64

// ---------------------------------------------------------------------------
// Fused kernel: one block per (b,n) plane.
//   1. warp 0 gathers the matched keypoint via one-hot reduction
//   2. whole block zeroes its 256 KB plane (coalesced float4 stores)
//   3. __syncthreads (orders the intra-block global stores)
//   4. threads 0..npix-1 overwrite the <=6x6 affected window with the
//      analytic "bilinear-scatter then 5x5 gaussian blur" value:
//      out[p] = sum over 4 corners c of w_c * GK5[c - p + 2]
// Planes are disjoint per block -> no atomics, no inter-block ordering.
// ---------------------------------------------------------------------------
__global__ void __launch_bounds__(THREADS)
fused_kernel(const float* __restrict__ Xg,
             const float* __restrict__ kp,
             const float* __restrict__ gk,
             float* __restrict__ out) {
    __shared__ float s_gk[25];
    __shared__ float s_red[3];   // sum(Xg*kx), sum(Xg*ky), sum(Xg) = mask

    const int row = blockIdx.x;      // b*N + n
    const int b   = row >> 5;        // N = 32
    const int tid = threadIdx.x;

    if (tid < 25) s_gk[tid] = gk[tid];   // gk[0][0] plane: the 5x5 kernel

    if (tid < 32) {
        float xg = Xg[row * NN + tid];
        float kx = kp[(b * NN + tid) * 2 + 0];
        float ky = kp[(b * NN + tid) * 2 + 1];
        float sx = xg * kx, sy = xg * ky, sm = xg;
        #pragma unroll
        for (int o = 16; o; o >>= 1) {
            sx += __shfl_down_sync(0xffffffffu, sx, o);
            sy += __shfl_down_sync(0xffffffffu, sy, o);
            sm += __shfl_down_sync(0xffffffffu, sm, o);
        }
        if (tid == 0) { s_red[0] = sx; s_red[1] = sy; s_red[2] = sm; }
    }

    // ---- zero this plane (bandwidth-bound part) ----
    float4* __restrict__ p4 = (float4*)(out + (size_t)row * PLANE);
    const float4 z = make_float4(0.f, 0.f, 0.f, 0.f);
    #pragma unroll
    for (int k = 0; k < ITERS; k++) {
        p4[tid + k * THREADS] = z;
    }

    __syncthreads();   // reduction results + plane zeros visible block-wide

    const float mask = s_red[2];
    if (mask == 0.f) return;   // row fully masked -> stays zero

    const float x = s_red[0] * (1.f / 16.f) - 0.5f;
    const float y = s_red[1] * (1.f / 16.f) - 0.5f;

    const float lox = fminf(fmaxf(floorf(x), 0.f), (float)(WW - 1));
    const float loy = fminf(fmaxf(floorf(y), 0.f), (float)(HH - 1));
    const float hix = fminf(fmaxf(ceilf(x),  0.f), (float)(WW - 1));
    const float hiy = fminf(fmaxf(ceilf(y),  0.f), (float)(HH - 1));

    const float upx = x - lox, upy = y - loy;
    const float wx0 = 1.f - upx, wx1 = upx;
    const float wy0 = 1.f - upy, wy1 = upy;

    const int x0 = (int)lox, x1 = (int)hix;
    const int y0 = (int)loy, y1 = (int)hiy;

    // affected window: rows [y0-2, y1+2], cols [x0-2, x1+2]  (spans <= 6x6)
    const int nx = x1 - x0 + 5;
    const int ny = y1 - y0 + 5;
    const int npix = nx * ny;                // <= 36

    float* plane = (float*)p4;

    if (tid < npix) {
        const int dy = tid / nx, dx = tid - dy * nx;
        const int oy = y0 - 2 + dy;
        const int ox = x0 - 2 + dx;
        if (oy >= 0 && oy < HH && ox >= 0 && ox < WW) {
            const int ry0 = oy - y0 + 2, ry1 = oy - y1 + 2;
            const int rx0 = ox - x0 + 2, rx1 = ox - x1 + 2;

            const bool by0 = (ry0 >= 0) & (ry0 < 5);
            const bool by1 = (ry1 >= 0) & (ry1 < 5);
            const bool bx0 = (rx0 >= 0) & (rx0 < 5);
            const bool bx1 = (rx1 >= 0) & (rx1 < 5);

            const float g00 = (by0 & bx0) ? s_gk[ry0 * 5 + rx0] : 0.f;
            const float g01 = (by0 & bx1) ? s_gk[ry0 * 5 + rx1] : 0.f;
            const float g10 = (by1 & bx0) ? s_gk[ry1 * 5 + rx0] : 0.f;
            const float g11 = (by1 & bx1) ? s_gk[ry1 * 5 + rx1] : 0.f;

            const float v = wy0 * wx0 * g00 + wy0 * wx1 * g01
                          + wy1 * wx0 * g10 + wy1 * wx1 * g11;

            plane[oy * WW + ox] = v * mask;   // mask == 1 here
        }
    }
}

extern "C" void kernel_launch(void* const* d_in, const int* in_sizes, int n_in,
                              void* d_out, int out_size) {
    const float* Xg = (const float*)d_in[0];   // (B, N, N)
    const float* kp = (const float*)d_in[1];   // (B, N, 2)
    const float* gk = (const float*)d_in[2];   // (N, 1, 5, 5)
    float* out = (float*)d_out;                // (B, N, H*W) fp32

    fused_kernel<<<ROWS, THREADS>>>(Xg, kp, gk, out);
}

// round 3
// speedup vs baseline: 1.5299x; 1.1237x over previous
#include <cuda_runtime.h>

// Problem shape (fixed by setup_inputs): B=16, N=32, H=W=256
#define HH 256
#define WW 256
#define BB 16
#define NN 32
#define ROWS (BB * NN)            // 512 (b,n) planes
#define PLANE (HH * WW)           // 65536 floats = 256 KB per plane
#define CHUNKS_PER_PLANE 8        // 32 image rows per chunk = 32 KB
#define CHUNK_IMROWS (HH / CHUNKS_PER_PLANE)       // 32
#define CHUNK_FLOATS (PLANE / CHUNKS_PER_PLANE)    // 8192
#define THREADS 256
#define CHUNK_F4 (CHUNK_FLOATS / 4)                // 2048
#define ITERS (CHUNK_F4 / THREADS)                 // 8
#define GRID (ROWS * CHUNKS_PER_PLANE)             // 4096

// ---------------------------------------------------------------------------
// One block per (plane, chunk). Block zeroes its 32-KB chunk (coalesced
// float4 stores), then overwrites the analytic blur values for the <=6x6
// affected window pixels that fall inside its own 32-row chunk. All
// zero->overwrite ordering is intra-block (__syncthreads), so no cross-block
// hazards exist. Keypoint gather is recomputed per block (cheap, L2-hit).
// ---------------------------------------------------------------------------
__global__ void __launch_bounds__(THREADS)
fused_kernel(const float* __restrict__ Xg,
             const float* __restrict__ kp,
             const float* __restrict__ gk,
             float* __restrict__ out) {
    __shared__ float s_gk[25];
    __shared__ float s_red[3];   // sum(Xg*kx), sum(Xg*ky), sum(Xg) = mask

    const int blk   = blockIdx.x;
    const int row   = blk >> 3;              // plane index: b*N + n
    const int sub   = blk & (CHUNKS_PER_PLANE - 1);
    const int b     = row >> 5;              // N = 32
    const int tid   = threadIdx.x;
    const int r0    = sub * CHUNK_IMROWS;    // first image row of this chunk

    if (tid < 25) s_gk[tid] = gk[tid];       // gk[0][0] plane: the 5x5 kernel

    if (tid < 32) {
        float xg = Xg[row * NN + tid];
        float kx = kp[(b * NN + tid) * 2 + 0];
        float ky = kp[(b * NN + tid) * 2 + 1];
        float sx = xg * kx, sy = xg * ky, sm = xg;
        #pragma unroll
        for (int o = 16; o; o >>= 1) {
            sx += __shfl_down_sync(0xffffffffu, sx, o);
            sy += __shfl_down_sync(0xffffffffu, sy, o);
            sm += __shfl_down_sync(0xffffffffu, sm, o);
        }
        if (tid == 0) { s_red[0] = sx; s_red[1] = sy; s_red[2] = sm; }
    }

    // ---- zero this chunk (bandwidth-bound part) ----
    float4* __restrict__ p4 =
        (float4*)(out + (size_t)row * PLANE + (size_t)sub * CHUNK_FLOATS);
    const float4 z = make_float4(0.f, 0.f, 0.f, 0.f);
    #pragma unroll
    for (int k = 0; k < ITERS; k++) {
        p4[tid + k * THREADS] = z;
    }

    __syncthreads();   // reduction results + chunk zeros visible block-wide

    const float mask = s_red[2];
    if (mask == 0.f) return;     // row fully masked -> stays zero

    const float x = s_red[0] * (1.f / 16.f) - 0.5f;
    const float y = s_red[1] * (1.f / 16.f) - 0.5f;

    const float lox = fminf(fmaxf(floorf(x), 0.f), (float)(WW - 1));
    const float loy = fminf(fmaxf(floorf(y), 0.f), (float)(HH - 1));
    const float hix = fminf(fmaxf(ceilf(x),  0.f), (float)(WW - 1));
    const float hiy = fminf(fmaxf(ceilf(y),  0.f), (float)(HH - 1));

    const float upx = x - lox, upy = y - loy;
    const float wx0 = 1.f - upx, wx1 = upx;
    const float wy0 = 1.f - upy, wy1 = upy;

    const int x0 = (int)lox, x1 = (int)hix;
    const int y0 = (int)loy, y1 = (int)hiy;

    // affected window: rows [y0-2, y1+2], cols [x0-2, x1+2]  (spans <= 6x6)
    const int nx = x1 - x0 + 5;
    const int ny = y1 - y0 + 5;
    const int npix = nx * ny;                // <= 36

    float* plane = out + (size_t)row * PLANE;

    if (tid < npix) {
        const int dy = tid / nx, dx = tid - dy * nx;
        const int oy = y0 - 2 + dy;
        const int ox = x0 - 2 + dx;
        // only pixels inside THIS block's chunk (keeps ordering intra-block)
        if (oy >= r0 && oy < r0 + CHUNK_IMROWS && ox >= 0 && ox < WW) {
            const int ry0 = oy - y0 + 2, ry1 = oy - y1 + 2;
            const int rx0 = ox - x0 + 2, rx1 = ox - x1 + 2;

            const bool by0 = (ry0 >= 0) & (ry0 < 5);
            const bool by1 = (ry1 >= 0) & (ry1 < 5);
            const bool bx0 = (rx0 >= 0) & (rx0 < 5);
            const bool bx1 = (rx1 >= 0) & (rx1 < 5);

            const float g00 = (by0 & bx0) ? s_gk[ry0 * 5 + rx0] : 0.f;
            const float g01 = (by0 & bx1) ? s_gk[ry0 * 5 + rx1] : 0.f;
            const float g10 = (by1 & bx0) ? s_gk[ry1 * 5 + rx0] : 0.f;
            const float g11 = (by1 & bx1) ? s_gk[ry1 * 5 + rx1] : 0.f;

            const float v = wy0 * wx0 * g00 + wy0 * wx1 * g01
                          + wy1 * wx0 * g10 + wy1 * wx1 * g11;

            plane[oy * WW + ox] = v * mask;   // mask == 1 here
        }
    }
}

extern "C" void kernel_launch(void* const* d_in, const int* in_sizes, int n_in,
                              void* d_out, int out_size) {
    const float* Xg = (const float*)d_in[0];   // (B, N, N)
    const float* kp = (const float*)d_in[1];   // (B, N, 2)
    const float* gk = (const float*)d_in[2];   // (N, 1, 5, 5)
    float* out = (float*)d_out;                // (B, N, H*W) fp32

    fused_kernel<<<GRID, THREADS>>>(Xg, kp, gk, out);
}

// round 4
// speedup vs baseline: 1.6140x; 1.0549x over previous
#include <cuda_runtime.h>

// Problem shape (fixed by setup_inputs): B=16, N=32, H=W=256
#define HH 256
#define WW 256
#define BB 16
#define NN 32
#define ROWS (BB * NN)            // 512 (b,n) planes
#define PLANE (HH * WW)           // 65536 floats = 256 KB per plane
#define CHUNKS_PER_PLANE 16       // 16 image rows per chunk = 16 KB
#define CHUNK_IMROWS (HH / CHUNKS_PER_PLANE)       // 16
#define CHUNK_FLOATS (PLANE / CHUNKS_PER_PLANE)    // 4096
#define THREADS 256
#define CHUNK_F4 (CHUNK_FLOATS / 4)                // 1024
#define ITERS (CHUNK_F4 / THREADS)                 // 4
#define GRID (ROWS * CHUNKS_PER_PLANE)             // 8192

// ---------------------------------------------------------------------------
// One block per (plane, chunk). Block zeroes its 16-KB chunk with streaming
// (evict-first) float4 stores, then overwrites the analytic blur values for
// the <=6x6 affected-window pixels that fall inside its own 16-row chunk.
// Zero->overwrite ordering stays intra-block (__syncthreads); planes/chunks
// are disjoint across blocks -> no cross-block hazards, no atomics.
// ---------------------------------------------------------------------------
__global__ void __launch_bounds__(THREADS)
fused_kernel(const float* __restrict__ Xg,
             const float* __restrict__ kp,
             const float* __restrict__ gk,
             float* __restrict__ out) {
    __shared__ float s_gk[25];
    __shared__ float s_red[3];   // sum(Xg*kx), sum(Xg*ky), sum(Xg) = mask

    const int blk   = blockIdx.x;
    const int row   = blk >> 4;                        // plane index: b*N + n
    const int sub   = blk & (CHUNKS_PER_PLANE - 1);
    const int b     = row >> 5;                        // N = 32
    const int tid   = threadIdx.x;
    const int r0    = sub * CHUNK_IMROWS;              // first image row of chunk

    if (tid < 25) s_gk[tid] = gk[tid];                 // gk[0][0]: the 5x5 kernel

    if (tid < 32) {
        float xg = Xg[row * NN + tid];
        float kx = kp[(b * NN + tid) * 2 + 0];
        float ky = kp[(b * NN + tid) * 2 + 1];
        float sx = xg * kx, sy = xg * ky, sm = xg;
        #pragma unroll
        for (int o = 16; o; o >>= 1) {
            sx += __shfl_down_sync(0xffffffffu, sx, o);
            sy += __shfl_down_sync(0xffffffffu, sy, o);
            sm += __shfl_down_sync(0xffffffffu, sm, o);
        }
        if (tid == 0) { s_red[0] = sx; s_red[1] = sy; s_red[2] = sm; }
    }

    // ---- zero this chunk: streaming 128-bit stores (evict-first in L2) ----
    float4* __restrict__ p4 =
        (float4*)(out + (size_t)row * PLANE + (size_t)sub * CHUNK_FLOATS);
    const float4 z = make_float4(0.f, 0.f, 0.f, 0.f);
    #pragma unroll
    for (int k = 0; k < ITERS; k++) {
        __stcs(&p4[tid + k * THREADS], z);
    }

    __syncthreads();   // reduction results + chunk zeros visible block-wide

    const float mask = s_red[2];
    if (mask == 0.f) return;     // row fully masked -> stays zero

    const float x = s_red[0] * (1.f / 16.f) - 0.5f;
    const float y = s_red[1] * (1.f / 16.f) - 0.5f;

    const float lox = fminf(fmaxf(floorf(x), 0.f), (float)(WW - 1));
    const float loy = fminf(fmaxf(floorf(y), 0.f), (float)(HH - 1));
    const float hix = fminf(fmaxf(ceilf(x),  0.f), (float)(WW - 1));
    const float hiy = fminf(fmaxf(ceilf(y),  0.f), (float)(HH - 1));

    const float upx = x - lox, upy = y - loy;
    const float wx0 = 1.f - upx, wx1 = upx;
    const float wy0 = 1.f - upy, wy1 = upy;

    const int x0 = (int)lox, x1 = (int)hix;
    const int y0 = (int)loy, y1 = (int)hiy;

    // affected window: rows [y0-2, y1+2], cols [x0-2, x1+2]  (spans <= 6x6)
    const int nx = x1 - x0 + 5;
    const int ny = y1 - y0 + 5;
    const int npix = nx * ny;                // <= 36

    float* plane = out + (size_t)row * PLANE;

    if (tid < npix) {
        const int dy = tid / nx, dx = tid - dy * nx;
        const int oy = y0 - 2 + dy;
        const int ox = x0 - 2 + dx;
        // only pixels inside THIS block's chunk (keeps ordering intra-block)
        if (oy >= r0 && oy < r0 + CHUNK_IMROWS && ox >= 0 && ox < WW) {
            const int ry0 = oy - y0 + 2, ry1 = oy - y1 + 2;
            const int rx0 = ox - x0 + 2, rx1 = ox - x1 + 2;

            const bool by0 = (ry0 >= 0) & (ry0 < 5);
            const bool by1 = (ry1 >= 0) & (ry1 < 5);
            const bool bx0 = (rx0 >= 0) & (rx0 < 5);
            const bool bx1 = (rx1 >= 0) & (rx1 < 5);

            const float g00 = (by0 & bx0) ? s_gk[ry0 * 5 + rx0] : 0.f;
            const float g01 = (by0 & bx1) ? s_gk[ry0 * 5 + rx1] : 0.f;
            const float g10 = (by1 & bx0) ? s_gk[ry1 * 5 + rx0] : 0.f;
            const float g11 = (by1 & bx1) ? s_gk[ry1 * 5 + rx1] : 0.f;

            const float v = wy0 * wx0 * g00 + wy0 * wx1 * g01
                          + wy1 * wx0 * g10 + wy1 * wx1 * g11;

            plane[oy * WW + ox] = v * mask;   // mask == 1 here
        }
    }
}

extern "C" void kernel_launch(void* const* d_in, const int* in_sizes, int n_in,
                              void* d_out, int out_size) {
    const float* Xg = (const float*)d_in[0];   // (B, N, N)
    const float* kp = (const float*)d_in[1];   // (B, N, 2)
    const float* gk = (const float*)d_in[2];   // (N, 1, 5, 5)
    float* out = (float*)d_out;                // (B, N, H*W) fp32

    fused_kernel<<<GRID, THREADS>>>(Xg, kp, gk, out);
}